// round 17
// baseline (speedup 1.0000x reference)
#include <cuda_runtime.h>
#include <cuda_bf16.h>
#include <math.h>
#include <cfloat>
#include <cstdint>

// ===========================================================================
// MIL-NCE head: s = (v @ t^T)/0.1, N=4096, T=4, D=256 (NT=16384)
// Outputs: [loss, recall1, recall5, recall10, avg_rank]
//
//  K0 init   : rmax <- -inf, cnt <- 0
//  K1 split  : fp32 -> 2x bf16 splits of v and t
//  K2 gemm   : mma.sync bf16 3-product GEMM, 64x128 CTA tile, 2 CTAs/SM,
//              chunked into 4 row stripes; S -> scratch + exact row maxes
//  K3 stats  : 32x128 smem tile (22KB -> co-resident with gemm), chunked,
//              runs on a SECOND STREAM overlapping the next gemm chunk.
//              Rank counts (packed u8x4), row sumexp (vs global rmax),
//              tile-local col (max,sumexp) pairs.
//  K4 rowfin : warp-per-row deterministic msmerge of partials -> loss+metrics
//  K5 reduce : deterministic means
// ===========================================================================

namespace {
constexpr int N  = 4096;
constexpr int T  = 4;
constexpr int NT = 16384;
constexpr int D  = 256;
constexpr float SCALE   = 10.0f;
constexpr float LSE_CUT = 30.0f;

constexpr int BMG = 64;                     // gemm CTA tile rows
constexpr int BN  = 128;                    // gemm CTA tile cols
constexpr int KC = 64;                      // K chunk (SW128: 128B rows)
constexpr int NCHUNK = D / KC;              // 4
constexpr int CTILE = NT / BN;              // 128
constexpr int RTG   = N / BMG;              // 64 gemm row-tiles
constexpr int RT32  = N / 32;               // 128 stats row-tiles

constexpr int NROWCHUNK = 4;                // pipeline chunks (1024 rows each)
constexpr int GEMM_YPC  = RTG / NROWCHUNK;  // 16
constexpr int STAT_YPC  = RT32 / NROWCHUNK; // 32

constexpr int NA = N * D;
constexpr int NB = NT * D;

constexpr int ATILE_B  = BMG * KC * 2;      // 8192
constexpr int BTILE_B  = BN  * KC * 2;      // 16384
constexpr int STAGE_B  = 2 * ATILE_B + 2 * BTILE_B;  // 49152
constexpr int GEMM_SMEM = 2 * STAGE_B;      // 98304 -> 2 CTA/SM

constexpr int SPAD = 132;                   // stats tile row pitch (words)
}

// ------------------------- device scratch ---------------------------------
__device__ float          g_S[(size_t)N * NT];   // 256 MB
__device__ __nv_bfloat16  g_As[2][NA];
__device__ __nv_bfloat16  g_Bs[2][NB];
__device__ int            g_rmax[N];
__device__ int            g_cnt[N][T];
__device__ float2         g_cpartMS[RT32][NT];   // col (max,sumexp) per 32-row tile
__device__ float          g_rspart[CTILE][N];    // row partial sumexp per col-tile
__device__ float          g_rowout[N][5];

// ------------------------- helpers ----------------------------------------
__device__ __forceinline__ int enc_f(float f) {
    int i = __float_as_int(f);
    return i >= 0 ? i : i ^ 0x7fffffff;
}
__device__ __forceinline__ float dec_f(int i) {
    return __int_as_float(i >= 0 ? i : i ^ 0x7fffffff);
}
__device__ __forceinline__ uint32_t smem_u32(const void* p) {
    uint32_t a;
    asm("{ .reg .u64 t; cvta.to.shared.u64 t, %1; cvt.u32.u64 %0, t; }" : "=r"(a) : "l"(p));
    return a;
}
__device__ __forceinline__ uint32_t sw128(uint32_t b) { return b ^ ((b >> 3) & 0x70); }

__device__ __forceinline__ void ldsm4(uint32_t* r, uint32_t addr) {
    asm volatile("ldmatrix.sync.aligned.m8n8.x4.shared.b16 {%0,%1,%2,%3}, [%4];"
        : "=r"(r[0]), "=r"(r[1]), "=r"(r[2]), "=r"(r[3]) : "r"(addr));
}
__device__ __forceinline__ void mma_bf16(float* d, const uint32_t* a, uint32_t b0, uint32_t b1) {
    asm volatile("mma.sync.aligned.m16n8k16.row.col.f32.bf16.bf16.f32 "
        "{%0,%1,%2,%3}, {%4,%5,%6,%7}, {%8,%9}, {%0,%1,%2,%3};"
        : "+f"(d[0]), "+f"(d[1]), "+f"(d[2]), "+f"(d[3])
        : "r"(a[0]), "r"(a[1]), "r"(a[2]), "r"(a[3]), "r"(b0), "r"(b1));
}
__device__ __forceinline__ void cp16(uint32_t dst, const void* src) {
    asm volatile("cp.async.cg.shared.global [%0], [%1], 16;" :: "r"(dst), "l"(src));
}
#define CP_COMMIT() asm volatile("cp.async.commit_group;" ::: "memory")
#define CP_WAIT(n)  asm volatile("cp.async.wait_group %0;" :: "n"(n) : "memory")

// (m,s) logsumexp-pair merge, deterministic given fixed call order
__device__ __forceinline__ void msmerge(float& m, float& s, float m2, float s2) {
    float M = fmaxf(m, m2);
    s = s * expf(m - M) + s2 * expf(m2 - M);
    m = M;
}

// ===========================================================================
// K0: init
__global__ void init_kernel() {
    int i = blockIdx.x * 256 + threadIdx.x;
    if (i < N)  g_rmax[i] = (int)0x80000000;
    if (i < NT) g_cnt[i >> 2][i & 3] = 0;
}

// ===========================================================================
// K1: 2-way bf16 split
__global__ __launch_bounds__(256)
void split_kernel(const float* __restrict__ v, const float* __restrict__ t) {
    int i = blockIdx.x * 256 + threadIdx.x;
    if (i >= NA + NB) return;
    float a = (i < NA) ? v[i] : t[i - NA];
    __nv_bfloat16 h0 = __float2bfloat16(a);
    float r1 = a - __bfloat162float(h0);
    __nv_bfloat16 h1 = __float2bfloat16(r1);
    if (i < NA) { g_As[0][i] = h0; g_As[1][i] = h1; }
    else { int j = i - NA; g_Bs[0][j] = h0; g_Bs[1][j] = h1; }
}

// ===========================================================================
// K2: HMMA GEMM, 64x128 CTA tile, 8 warps 2(m) x 4(n), warp tile 32x32.
__global__ __launch_bounds__(256, 2)
void gemm_mma(int bm0) {
    extern __shared__ char smem[];
    const uint32_t sb = smem_u32(smem);
    const int tid = threadIdx.x, lane = tid & 31, wid = tid >> 5;
    const int wm = wid >> 2, wn = wid & 3;
    const int bn = blockIdx.x, bm = bm0 + blockIdx.y;

    const int a_r    = lane & 15;
    const int a_koff = (lane >> 4) * 16;
    const int b_r    = (lane & 7) + ((lane & 16) >> 1);
    const int b_koff = (lane & 8) << 1;
    const uint32_t a_xm = (uint32_t)(a_r & 7) << 4;
    const uint32_t b_xm = (uint32_t)(b_r & 7) << 4;

    uint32_t a_rowb[2], b_rowb[2];
    #pragma unroll
    for (int mi = 0; mi < 2; mi++) a_rowb[mi] = (uint32_t)(wm * 32 + mi * 16 + a_r) * 128;
    #pragma unroll
    for (int p = 0; p < 2; p++)    b_rowb[p]  = (uint32_t)(wn * 32 + p * 16 + b_r) * 128;

    float acc[2][4][4];
    #pragma unroll
    for (int mi = 0; mi < 2; mi++)
        #pragma unroll
        for (int nf = 0; nf < 4; nf++)
            #pragma unroll
            for (int q = 0; q < 4; q++) acc[mi][nf][q] = 0.f;

    auto prefetch = [&](int stage, int kc) {
        const int k0 = kc * KC;
        #pragma unroll
        for (int i = 0; i < 12; i++) {
            int g = i * 256 + tid;
            uint32_t dst;
            const __nv_bfloat16* src;
            if (g < 1024) {
                int s = g >> 9, idx = g & 511;
                int r = idx >> 3, b = idx & 7;
                src = g_As[s] + (size_t)(bm * BMG + r) * D + k0 + b * 8;
                dst = sb + stage * STAGE_B + s * ATILE_B + sw128(r * 128 + b * 16);
            } else {
                int g2 = g - 1024;
                int s = g2 >> 10, idx = g2 & 1023;
                int r = idx >> 3, b = idx & 7;
                src = g_Bs[s] + (size_t)(bn * BN + r) * D + k0 + b * 8;
                dst = sb + stage * STAGE_B + 2 * ATILE_B + s * BTILE_B + sw128(r * 128 + b * 16);
            }
            cp16(dst, src);
        }
    };

    prefetch(0, 0);
    CP_COMMIT();

    for (int kc = 0; kc < NCHUNK; kc++) {
        if (kc < NCHUNK - 1) { prefetch((kc + 1) & 1, kc + 1); CP_COMMIT(); CP_WAIT(1); }
        else { CP_WAIT(0); }
        __syncthreads();

        const uint32_t base  = sb + (kc & 1) * STAGE_B;
        const uint32_t baseB = base + 2 * ATILE_B;
        #pragma unroll
        for (int k16 = 0; k16 < 4; k16++) {
            const uint32_t kb = k16 * 32;
            uint32_t af[2][2][4];
            #pragma unroll
            for (int s2 = 0; s2 < 2; s2++)
                #pragma unroll
                for (int mi = 0; mi < 2; mi++)
                    ldsm4(af[s2][mi], base + s2 * ATILE_B + a_rowb[mi] + ((kb + a_koff) ^ a_xm));
            uint32_t bf[2][2][4];
            #pragma unroll
            for (int s2 = 0; s2 < 2; s2++)
                #pragma unroll
                for (int p = 0; p < 2; p++)
                    ldsm4(bf[s2][p], baseB + s2 * BTILE_B + b_rowb[p] + ((kb + b_koff) ^ b_xm));

            #pragma unroll
            for (int mi = 0; mi < 2; mi++)
                #pragma unroll
                for (int nf = 0; nf < 4; nf++) {
                    const uint32_t* bp0 = &bf[0][nf >> 1][(nf & 1) * 2];
                    const uint32_t* bp1 = &bf[1][nf >> 1][(nf & 1) * 2];
                    mma_bf16(acc[mi][nf], af[0][mi], bp0[0], bp0[1]);
                    mma_bf16(acc[mi][nf], af[0][mi], bp1[0], bp1[1]);
                    mma_bf16(acc[mi][nf], af[1][mi], bp0[0], bp0[1]);
                }
        }
        __syncthreads();
    }

    // ---- epilogue: scale, store S, exact ROW maxes only ----
    #pragma unroll
    for (int mi = 0; mi < 2; mi++)
        #pragma unroll
        for (int nf = 0; nf < 4; nf++)
            #pragma unroll
            for (int q = 0; q < 4; q++) acc[mi][nf][q] *= SCALE;

    const int qr = lane >> 2;
    const int qc = (lane & 3) * 2;

    #pragma unroll
    for (int mi = 0; mi < 2; mi++)
        #pragma unroll
        for (int h = 0; h < 2; h++) {
            int row = bm * BMG + wm * 32 + mi * 16 + h * 8 + qr;
            float* dst = g_S + (size_t)row * NT + (size_t)bn * BN + wn * 32 + qc;
            #pragma unroll
            for (int nf = 0; nf < 4; nf++)
                *reinterpret_cast<float2*>(dst + nf * 8) =
                    make_float2(acc[mi][nf][2 * h], acc[mi][nf][2 * h + 1]);
        }

    #pragma unroll
    for (int mi = 0; mi < 2; mi++)
        #pragma unroll
        for (int h = 0; h < 2; h++) {
            float m = -FLT_MAX;
            #pragma unroll
            for (int nf = 0; nf < 4; nf++)
                m = fmaxf(m, fmaxf(acc[mi][nf][2 * h], acc[mi][nf][2 * h + 1]));
            m = fmaxf(m, __shfl_xor_sync(0xffffffffu, m, 1));
            m = fmaxf(m, __shfl_xor_sync(0xffffffffu, m, 2));
            if ((lane & 3) == 0)
                atomicMax(&g_rmax[bm * BMG + wm * 32 + mi * 16 + h * 8 + qr], enc_f(m));
        }
}

// ===========================================================================
// K3: stats — 32x128 tile (~22KB smem, co-resident with gemm CTAs).
// Row pass: rank counts (packed u8x4) + row sumexp vs global rmax.
// Col pass: tile-local (max, sumexp).
__global__ __launch_bounds__(256)
void stats_kernel(int rt0) {
    __shared__ float    tile[32 * SPAD];     // 16896 B
    __shared__ float    sp[32][4];
    __shared__ float    srm[32];
    __shared__ uint32_t scntP[8][32];        // packed 4x u8 counts per seg
    __shared__ float    srs8[8][32];
    __shared__ float    scsM[2][128], scsS[2][128];

    const int tid = threadIdx.x;
    const int ct = blockIdx.x;
    const int rt = rt0 + blockIdx.y;
    const int c0 = ct * BN, r0 = rt * 32;

    // stage 32x128 block (coalesced float4)
    #pragma unroll
    for (int i = 0; i < 4; i++) {
        int idx = i * 256 + tid;             // 0..1023 float4 chunks
        int r = idx >> 5, c4 = idx & 31;
        float4 v = *reinterpret_cast<const float4*>(
            g_S + (size_t)(r0 + r) * NT + c0 + c4 * 4);
        *reinterpret_cast<float4*>(&tile[r * SPAD + c4 * 4]) = v;
    }
    if (tid < 32) {
        int gr = r0 + tid;
        srm[tid] = dec_f(g_rmax[gr]);
        #pragma unroll
        for (int t = 0; t < 4; t++)
            sp[tid][t] = g_S[(size_t)gr * NT + gr * 4 + t];
    }
    __syncthreads();

    // ---- row pass: thread = (row, 16-col segment) ----
    {
        const int r = tid >> 3, seg = tid & 7;
        const float p0 = sp[r][0], p1 = sp[r][1], p2 = sp[r][2], p3 = sp[r][3];
        const float rm = srm[r], thr = rm - LSE_CUT;
        int c0n = 0, c1n = 0, c2n = 0, c3n = 0;
        float rs = 0.f;
        const float* tp = &tile[r * SPAD + seg * 16];
        #pragma unroll
        for (int i = 0; i < 8; i++) {
            float2 xv = *reinterpret_cast<const float2*>(tp + i * 2);
            c0n += (xv.x > p0) + (xv.y > p0);
            c1n += (xv.x > p1) + (xv.y > p1);
            c2n += (xv.x > p2) + (xv.y > p2);
            c3n += (xv.x > p3) + (xv.y > p3);
            if (xv.x > thr) rs += expf(xv.x - rm);
            if (xv.y > thr) rs += expf(xv.y - rm);
        }
        scntP[seg][r] = (uint32_t)c0n | ((uint32_t)c1n << 8) |
                        ((uint32_t)c2n << 16) | ((uint32_t)c3n << 24);
        srs8[seg][r] = rs;
    }

    // ---- col pass: thread = (col, 16-row half), tile-local (max,sum) ----
    {
        const int c = tid & 127, half = tid >> 7;
        const float* tp = &tile[(half * 16) * SPAD + c];
        float m = -FLT_MAX;
        #pragma unroll
        for (int r = 0; r < 16; r++) m = fmaxf(m, tp[r * SPAD]);
        const float thr = m - LSE_CUT;
        float cs = 0.f;
        #pragma unroll
        for (int r = 0; r < 16; r++) {
            float x = tp[r * SPAD];
            if (x > thr) cs += expf(x - m);
        }
        scsM[half][c] = m;
        scsS[half][c] = cs;
    }
    __syncthreads();

    if (tid < 128) {
        float m = scsM[0][tid], s = scsS[0][tid];
        msmerge(m, s, scsM[1][tid], scsS[1][tid]);
        g_cpartMS[rt][c0 + tid] = make_float2(m, s);
    }
    if (tid < 32) {
        uint32_t acc = 0;
        #pragma unroll
        for (int seg = 0; seg < 8; seg++) acc += scntP[seg][tid];
        #pragma unroll
        for (int t = 0; t < 4; t++)
            atomicAdd(&g_cnt[r0 + tid][t], (int)((acc >> (8 * t)) & 0xFF));
        float rs = 0.f;
        #pragma unroll
        for (int seg = 0; seg < 8; seg++) rs += srs8[seg][tid];
        g_rspart[ct][r0 + tid] = rs;
    }
}

// ===========================================================================
// K4: warp-per-row deterministic merge -> loss + metrics
__global__ __launch_bounds__(256)
void rowfin_kernel() {
    const int i = blockIdx.x * 8 + (threadIdx.x >> 5);
    const int lane = threadIdx.x & 31;

    // row sumexp total (all relative to global rmax)
    float rs = 0.f;
    for (int ct = lane; ct < CTILE; ct += 32) rs += g_rspart[ct][i];
    #pragma unroll
    for (int off = 16; off; off >>= 1)
        rs += __shfl_xor_sync(0xffffffffu, rs, off);

    // col partial merge: fixed deterministic order
    float m = -FLT_MAX, s = 0.f;
    #pragma unroll
    for (int t = 0; t < 4; t++)
        for (int k = lane; k < RT32; k += 32) {
            float2 f = g_cpartMS[k][i * 4 + t];
            msmerge(m, s, f.x, f.y);
        }
    #pragma unroll
    for (int off = 16; off; off >>= 1) {
        float m2 = __shfl_xor_sync(0xffffffffu, m, off);
        float s2 = __shfl_xor_sync(0xffffffffu, s, off);
        msmerge(m, s, m2, s2);
    }

    if (lane == 0) {
        float rm = dec_f(g_rmax[i]);
        msmerge(m, s, rm, rs);
        float denom = m + logf(s);

        float p[4];
        #pragma unroll
        for (int t = 0; t < 4; t++) p[t] = g_S[(size_t)i * NT + i * 4 + t];
        float pm = fmaxf(fmaxf(p[0], p[1]), fmaxf(p[2], p[3]));
        float nom = pm + logf(expf(p[0] - pm) + expf(p[1] - pm) +
                              expf(p[2] - pm) + expf(p[3] - pm));

        float r1 = 0.f, r5 = 0.f, r10 = 0.f, ar = 0.f;
        #pragma unroll
        for (int t = 0; t < 4; t++) {
            int rk = g_cnt[i][t];
            r1  += (rk < 1);
            r5  += (rk < 5);
            r10 += (rk < 10);
            ar  += (float)rk;
        }
        g_rowout[i][0] = denom - nom;
        g_rowout[i][1] = r1  * 0.25f;
        g_rowout[i][2] = r5  * 0.25f;
        g_rowout[i][3] = r10 * 0.25f;
        g_rowout[i][4] = ar  * 0.25f;
    }
}

// ===========================================================================
// K5: deterministic means
__global__ __launch_bounds__(256)
void final_kernel(float* __restrict__ out) {
    __shared__ double sacc[5][256];
    int tid = threadIdx.x;
    double a[5] = {0, 0, 0, 0, 0};
    for (int i = tid; i < N; i += 256)
        #pragma unroll
        for (int q = 0; q < 5; q++) a[q] += (double)g_rowout[i][q];
    #pragma unroll
    for (int q = 0; q < 5; q++) sacc[q][tid] = a[q];
    __syncthreads();
    for (int off = 128; off > 0; off >>= 1) {
        if (tid < off)
            #pragma unroll
            for (int q = 0; q < 5; q++) sacc[q][tid] += sacc[q][tid + off];
        __syncthreads();
    }
    if (tid == 0)
        #pragma unroll
        for (int q = 0; q < 5; q++) out[q] = (float)(sacc[q][0] / (double)N);
}

// ===========================================================================
extern "C" void kernel_launch(void* const* d_in, const int* in_sizes, int n_in,
                              void* d_out, int out_size) {
    const float* v = (const float*)d_in[0];   // [4096, 256]
    const float* t = (const float*)d_in[1];   // [16384, 256]
    (void)in_sizes; (void)n_in; (void)out_size;

    static int inited = 0;
    static cudaStream_t s2;
    static cudaEvent_t evG[NROWCHUNK], evS[NROWCHUNK];
    if (!inited) {
        cudaFuncSetAttribute(gemm_mma, cudaFuncAttributeMaxDynamicSharedMemorySize, GEMM_SMEM);
        cudaStreamCreateWithFlags(&s2, cudaStreamNonBlocking);
        for (int k = 0; k < NROWCHUNK; k++) {
            cudaEventCreateWithFlags(&evG[k], cudaEventDisableTiming);
            cudaEventCreateWithFlags(&evS[k], cudaEventDisableTiming);
        }
        inited = 1;
    }

    init_kernel<<<(NT + 255) / 256, 256>>>();
    split_kernel<<<(NA + NB + 255) / 256, 256>>>(v, t);

    for (int k = 0; k < NROWCHUNK; k++) {
        gemm_mma<<<dim3(CTILE, GEMM_YPC), 256, GEMM_SMEM>>>(k * GEMM_YPC);
        cudaEventRecord(evG[k], 0);
        cudaStreamWaitEvent(s2, evG[k], 0);
        stats_kernel<<<dim3(CTILE, STAT_YPC), 256, 0, s2>>>(k * STAT_YPC);
        cudaEventRecord(evS[k], s2);
    }
    for (int k = 0; k < NROWCHUNK; k++)
        cudaStreamWaitEvent(0, evS[k], 0);

    rowfin_kernel<<<N / 8, 256>>>();
    final_kernel<<<1, 256>>>((float*)d_out);
}